// round 5
// baseline (speedup 1.0000x reference)
#include <cuda_runtime.h>
#include <cuda_bf16.h>

#define H 128
#define MAXN 50000
#define MAXE 800000

// ---- scratch (static __device__ globals; no allocations allowed) ----
__device__ float d_gl[MAXN * H];        // q @ W_l^T
__device__ float d_gr[MAXN * H];        // q @ W_r^T
__device__ int   d_src[MAXE];           // int32 source indices (edge order)
__device__ int   d_dst[MAXE];           // int32 dest indices   (edge order)
__device__ int   d_cnt[MAXN];           // in-degree histogram
__device__ int   d_rowptr[MAXN + 1];    // CSR row pointers (by dst)
__device__ int   d_cursor[MAXN];        // scatter cursors
__device__ int   d_esrc[MAXE];          // CSR-ordered src per edge
__device__ float d_eenv[MAXE];          // CSR-ordered envelope per edge
__device__ int   d_is64;                // edge_index dtype flag

// Detect whether edge_index buffer holds int64 or int32.
// int32 data read as int64 pairs two node ids: v = lo + (hi<<32); hi != 0
// with prob (N-1)/N per word. Requiring 256 consecutive in-range int64
// words makes a false "int64" verdict probability ~(1/N)^256 — impossible.
__global__ void k_detect(const void* idx, long long n64, int N) {
    if (blockIdx.x == 0 && threadIdx.x == 0) {
        const long long* p = (const long long*)idx;
        int ok = 1;
        long long m = n64 < 256 ? n64 : 256;
        for (long long i = 0; i < m; i++) {
            long long v = p[i];
            if (v < 0 || v >= (long long)N) { ok = 0; break; }
        }
        d_is64 = ok;
    }
}

// Zero the histogram (must be reset every launch — graph replays).
__global__ void k_zero_cnt(int N) {
    int i = blockIdx.x * blockDim.x + threadIdx.x;
    if (i < N) d_cnt[i] = 0;
}

// Convert edge_index (either dtype) into packed int32 src/dst + histogram.
__global__ void k_prep(const void* idx, long long E) {
    long long i = (long long)blockIdx.x * blockDim.x + threadIdx.x;
    long long stride = (long long)gridDim.x * blockDim.x;
    int is64 = d_is64;
    if (is64) {
        const long long* p = (const long long*)idx;
        for (long long e = i; e < E; e += stride) {
            int s = (int)p[e];
            int d = (int)p[E + e];
            d_src[e] = s; d_dst[e] = d;
            atomicAdd(&d_cnt[d], 1);
        }
    } else {
        const int* p = (const int*)idx;
        for (long long e = i; e < E; e += stride) {
            int s = p[e];
            int d = p[E + e];
            d_src[e] = s; d_dst[e] = d;
            atomicAdd(&d_cnt[d], 1);
        }
    }
}

// Single-block exclusive scan over d_cnt -> d_rowptr / d_cursor.
__global__ void k_scan(int N, int E) {
    __shared__ int ssum[1024];
    int t = threadIdx.x;
    int chunk = (N + 1023) / 1024;
    int lo = t * chunk;
    int hi = lo + chunk; if (hi > N) hi = N;
    int s = 0;
    for (int i = lo; i < hi; i++) s += d_cnt[i];
    ssum[t] = s;
    __syncthreads();
    // Hillis-Steele inclusive scan over the 1024 per-thread sums
    for (int off = 1; off < 1024; off <<= 1) {
        int v = (t >= off) ? ssum[t - off] : 0;
        __syncthreads();
        ssum[t] += v;
        __syncthreads();
    }
    int base = (t > 0) ? ssum[t - 1] : 0;
    for (int i = lo; i < hi; i++) {
        d_rowptr[i] = base;
        d_cursor[i] = base;
        base += d_cnt[i];
    }
    if (t == 0) d_rowptr[N] = E;
}

// Scatter edges into CSR order; pre-gather env so the hot loop is contiguous.
__global__ void k_scatter(const float* __restrict__ env, long long E) {
    long long i = (long long)blockIdx.x * blockDim.x + threadIdx.x;
    long long stride = (long long)gridDim.x * blockDim.x;
    for (long long e = i; e < E; e += stride) {
        int d = d_dst[e];
        int pos = atomicAdd(&d_cursor[d], 1);
        d_esrc[pos] = d_src[e];
        d_eenv[pos] = env[e];
    }
}

// g_l = q @ W_l^T, g_r = q @ W_r^T.  W is [H][K] row-major (K=H=128).
// Block: 128 threads (thread t owns output channel h=t), 8 nodes per block.
#define NPB 8
#define KT  32
__global__ void k_gemm(const float* __restrict__ q,
                       const float* __restrict__ Wl,
                       const float* __restrict__ Wr, int N) {
    __shared__ float qs[NPB][H];
    __shared__ float wls[H][KT + 1];
    __shared__ float wrs[H][KT + 1];

    int t = threadIdx.x;
    int base = blockIdx.x * NPB;

    #pragma unroll
    for (int n = 0; n < NPB; n++) {
        int node = base + n;
        qs[n][t] = (node < N) ? q[(long long)node * H + t] : 0.0f;
    }

    float accl[NPB], accr[NPB];
    #pragma unroll
    for (int n = 0; n < NPB; n++) { accl[n] = 0.0f; accr[n] = 0.0f; }

    for (int k0 = 0; k0 < H; k0 += KT) {
        __syncthreads();
        for (int i = t; i < H * KT; i += 128) {
            int h = i >> 5, kk = i & 31;
            wls[h][kk] = Wl[h * H + k0 + kk];
            wrs[h][kk] = Wr[h * H + k0 + kk];
        }
        __syncthreads();
        #pragma unroll
        for (int kk = 0; kk < KT; kk++) {
            float wl = wls[t][kk];
            float wr = wrs[t][kk];
            #pragma unroll
            for (int n = 0; n < NPB; n++) {
                float qv = qs[n][k0 + kk];
                accl[n] = fmaf(qv, wl, accl[n]);
                accr[n] = fmaf(qv, wr, accr[n]);
            }
        }
    }

    #pragma unroll
    for (int n = 0; n < NPB; n++) {
        int node = base + n;
        if (node < N) {
            d_gl[(long long)node * H + t] = accl[n];
            d_gr[(long long)node * H + t] = accr[n];
        }
    }
}

// silu-dot helper: per-lane partial of aw . silu(a + b) over 4 channels.
__device__ __forceinline__ float silu_dot4(float4 a, float4 b, float4 aw4) {
    float x0 = a.x + b.x, x1 = a.y + b.y, x2 = a.z + b.z, x3 = a.w + b.w;
    float s0 = x0 / (1.0f + __expf(-x0));
    float s1 = x1 / (1.0f + __expf(-x1));
    float s2 = x2 / (1.0f + __expf(-x2));
    float s3 = x3 / (1.0f + __expf(-x3));
    return aw4.x * s0 + aw4.y * s1 + aw4.z * s2 + aw4.w * s3;
}

// CSR edge pass: one warp per dst node. gr[dst] loaded once; per edge we
// gather gl[src], compute v = (env+1e-7)*exp(p) (deferred-normalization
// softmax weight), and accumulate numerator + denominator in registers.
// Final write: out[d] = acc / vsum (exact softmax-weighted sum with 1/denom
// factored out). No atomics, no out init, no separate normalize pass.
// 2-way edge unroll overlaps the two shuffle-reduce chains for ILP.
__global__ void k_edge_csr(const float* __restrict__ aw,
                           float* __restrict__ out, int N) {
    int lane = threadIdx.x & 31;
    long long warpId = ((long long)blockIdx.x * blockDim.x + threadIdx.x) >> 5;
    long long nWarps = ((long long)gridDim.x * blockDim.x) >> 5;
    float4 aw4 = ((const float4*)aw)[lane];

    for (long long d = warpId; d < N; d += nWarps) {
        int start = d_rowptr[d];
        int end   = d_rowptr[d + 1];
        float4 b = ((const float4*)d_gr)[d * 32 + lane];

        float4 acc = make_float4(0.f, 0.f, 0.f, 0.f);
        float vsum = 0.0f;

        int i = start;
        for (; i + 1 < end; i += 2) {
            int s0 = d_esrc[i], s1 = d_esrc[i + 1];
            float4 a0 = ((const float4*)d_gl)[(long long)s0 * 32 + lane];
            float4 a1 = ((const float4*)d_gl)[(long long)s1 * 32 + lane];
            float p0 = silu_dot4(a0, b, aw4);
            float p1 = silu_dot4(a1, b, aw4);
            #pragma unroll
            for (int off = 16; off; off >>= 1) {
                p0 += __shfl_xor_sync(0xFFFFFFFFu, p0, off);
                p1 += __shfl_xor_sync(0xFFFFFFFFu, p1, off);
            }
            float v0 = (d_eenv[i]     + 1e-7f) * __expf(p0);
            float v1 = (d_eenv[i + 1] + 1e-7f) * __expf(p1);
            acc.x = fmaf(v0, a0.x, fmaf(v1, a1.x, acc.x));
            acc.y = fmaf(v0, a0.y, fmaf(v1, a1.y, acc.y));
            acc.z = fmaf(v0, a0.z, fmaf(v1, a1.z, acc.z));
            acc.w = fmaf(v0, a0.w, fmaf(v1, a1.w, acc.w));
            vsum += v0 + v1;
        }
        if (i < end) {
            int s0 = d_esrc[i];
            float4 a0 = ((const float4*)d_gl)[(long long)s0 * 32 + lane];
            float p0 = silu_dot4(a0, b, aw4);
            #pragma unroll
            for (int off = 16; off; off >>= 1)
                p0 += __shfl_xor_sync(0xFFFFFFFFu, p0, off);
            float v0 = (d_eenv[i] + 1e-7f) * __expf(p0);
            acc.x = fmaf(v0, a0.x, acc.x);
            acc.y = fmaf(v0, a0.y, acc.y);
            acc.z = fmaf(v0, a0.z, acc.z);
            acc.w = fmaf(v0, a0.w, acc.w);
            vsum += v0;
        }

        float inv = (end > start) ? 1.0f / vsum : 0.0f;
        float4 o;
        o.x = acc.x * inv; o.y = acc.y * inv;
        o.z = acc.z * inv; o.w = acc.w * inv;
        ((float4*)out)[d * 32 + lane] = o;
    }
}

extern "C" void kernel_launch(void* const* d_in, const int* in_sizes, int n_in,
                              void* d_out, int out_size) {
    const float* q   = (const float*)d_in[0];
    // d_in[1]=k, d_in[2]=v : unused by the reference module
    const float* env = (const float*)d_in[3];
    const float* Wl  = (const float*)d_in[4];
    const float* Wr  = (const float*)d_in[5];
    const float* aw  = (const float*)d_in[6];
    const void*  ei  = d_in[7];

    int N = in_sizes[0] / H;
    long long E = in_sizes[3];
    float* out = (float*)d_out;

    long long n64 = (long long)in_sizes[7] / 2;
    k_detect<<<1, 32>>>(ei, n64, N);
    k_zero_cnt<<<(N + 255) / 256, 256>>>(N);
    k_prep<<<1024, 256>>>(ei, E);
    k_scan<<<1, 1024>>>(N, (int)E);
    k_scatter<<<1024, 256>>>(env, E);

    k_gemm<<<(N + NPB - 1) / NPB, 128>>>(q, Wl, Wr, N);

    k_edge_csr<<<(N * 32 + 255) / 256, 256>>>(aw, out, N);
}

// round 7
// speedup vs baseline: 1.4973x; 1.4973x over previous
#include <cuda_runtime.h>
#include <cuda_bf16.h>

#define H 128
#define MAXN 50000
#define MAXE 800000
#define SCAN_T 256

// ---- scratch (static __device__ globals; no allocations allowed) ----
__device__ float d_gl[MAXN * H];        // q @ W_l^T
__device__ float d_gr[MAXN * H];        // q @ W_r^T
__device__ int   d_cnt[MAXN];           // in-degree histogram
__device__ int   d_rowptr[MAXN + 1];    // CSR row pointers (by dst)
__device__ int   d_cursor[MAXN];        // scatter cursors
__device__ int   d_bsum[SCAN_T];        // per-block scan sums
__device__ int   d_esrc[MAXE];          // CSR-ordered src per edge
__device__ float d_eenv[MAXE];          // CSR-ordered envelope per edge
__device__ int   d_is64;                // edge_index dtype flag

// ---- init + dtype detect, one kernel ----
// Block 0: 256 threads each validate one int64 word of edge_index; if all are
// in [0,N) the buffer is int64 (int32 data read as int64 pairs two ids and
// lands >= 2^32 with prob (N-1)/N per word; 256 words -> false verdict
// probability ~(1/N)^256). All blocks: zero the histogram.
__global__ void k_init_detect(const void* idx, long long n64, int N) {
    int i = blockIdx.x * blockDim.x + threadIdx.x;
    if (i < N) d_cnt[i] = 0;
    if (blockIdx.x == 0) {
        int t = threadIdx.x;
        long long m = n64 < 256 ? n64 : 256;
        int bad = 0;
        if (t < m) {
            long long v = ((const long long*)idx)[t];
            bad = (v < 0 || v >= (long long)N);
        }
        int any = __syncthreads_or(bad);
        if (t == 0) d_is64 = !any;
    }
}

// Histogram of destination degrees (reads edge_index directly).
__global__ void k_hist(const void* idx, long long E) {
    long long i = (long long)blockIdx.x * blockDim.x + threadIdx.x;
    long long stride = (long long)gridDim.x * blockDim.x;
    if (d_is64) {
        const long long* p = (const long long*)idx;
        for (long long e = i; e < E; e += stride)
            atomicAdd(&d_cnt[(int)p[E + e]], 1);
    } else {
        const int* p = (const int*)idx;
        for (long long e = i; e < E; e += stride)
            atomicAdd(&d_cnt[p[E + e]], 1);
    }
}

// ---- three-phase multi-block exclusive scan: d_cnt -> d_rowptr ----
__global__ void k_scan_local(int N) {
    __shared__ int sh[SCAN_T];
    int b = blockIdx.x, t = threadIdx.x;
    int i = b * SCAN_T + t;
    int v = (i < N) ? d_cnt[i] : 0;
    sh[t] = v;
    __syncthreads();
    #pragma unroll
    for (int off = 1; off < SCAN_T; off <<= 1) {
        int x = (t >= off) ? sh[t - off] : 0;
        __syncthreads();
        sh[t] += x;
        __syncthreads();
    }
    if (i < N) d_rowptr[i] = sh[t] - v;          // local exclusive
    if (t == SCAN_T - 1) d_bsum[b] = sh[t];      // block total
}

__global__ void k_scan_bsum(int nb) {
    __shared__ int sh[SCAN_T];
    int t = threadIdx.x;
    int v = (t < nb) ? d_bsum[t] : 0;
    sh[t] = v;
    __syncthreads();
    #pragma unroll
    for (int off = 1; off < SCAN_T; off <<= 1) {
        int x = (t >= off) ? sh[t - off] : 0;
        __syncthreads();
        sh[t] += x;
        __syncthreads();
    }
    if (t < nb) d_bsum[t] = sh[t] - v;           // exclusive block offsets
}

__global__ void k_scan_add(int N, int E) {
    int i = blockIdx.x * blockDim.x + threadIdx.x;
    if (i < N) {
        int r = d_rowptr[i] + d_bsum[blockIdx.x];
        d_rowptr[i] = r;
        d_cursor[i] = r;
    }
    if (i == 0) d_rowptr[N] = E;
}

// Scatter edges into CSR order (reads edge_index directly; gathers env so
// the hot loop reads it contiguously).
__global__ void k_scatter(const void* idx, const float* __restrict__ env,
                          long long E) {
    long long i = (long long)blockIdx.x * blockDim.x + threadIdx.x;
    long long stride = (long long)gridDim.x * blockDim.x;
    if (d_is64) {
        const long long* p = (const long long*)idx;
        for (long long e = i; e < E; e += stride) {
            int s = (int)p[e];
            int d = (int)p[E + e];
            int pos = atomicAdd(&d_cursor[d], 1);
            d_esrc[pos] = s;
            d_eenv[pos] = env[e];
        }
    } else {
        const int* p = (const int*)idx;
        for (long long e = i; e < E; e += stride) {
            int s = p[e];
            int d = p[E + e];
            int pos = atomicAdd(&d_cursor[d], 1);
            d_esrc[pos] = s;
            d_eenv[pos] = env[e];
        }
    }
}

// g_l = q @ W_l^T, g_r = q @ W_r^T.  W is [H][K] row-major (K=H=128).
// Block: 128 threads (thread t owns output channel h=t), 8 nodes per block.
#define NPB 8
#define KT  32
__global__ void k_gemm(const float* __restrict__ q,
                       const float* __restrict__ Wl,
                       const float* __restrict__ Wr, int N) {
    __shared__ float qs[NPB][H];
    __shared__ float wls[H][KT + 1];
    __shared__ float wrs[H][KT + 1];

    int t = threadIdx.x;
    int base = blockIdx.x * NPB;

    #pragma unroll
    for (int n = 0; n < NPB; n++) {
        int node = base + n;
        qs[n][t] = (node < N) ? q[(long long)node * H + t] : 0.0f;
    }

    float accl[NPB], accr[NPB];
    #pragma unroll
    for (int n = 0; n < NPB; n++) { accl[n] = 0.0f; accr[n] = 0.0f; }

    for (int k0 = 0; k0 < H; k0 += KT) {
        __syncthreads();
        for (int i = t; i < H * KT; i += 128) {
            int h = i >> 5, kk = i & 31;
            wls[h][kk] = Wl[h * H + k0 + kk];
            wrs[h][kk] = Wr[h * H + k0 + kk];
        }
        __syncthreads();
        #pragma unroll
        for (int kk = 0; kk < KT; kk++) {
            float wl = wls[t][kk];
            float wr = wrs[t][kk];
            #pragma unroll
            for (int n = 0; n < NPB; n++) {
                float qv = qs[n][k0 + kk];
                accl[n] = fmaf(qv, wl, accl[n]);
                accr[n] = fmaf(qv, wr, accr[n]);
            }
        }
    }

    #pragma unroll
    for (int n = 0; n < NPB; n++) {
        int node = base + n;
        if (node < N) {
            d_gl[(long long)node * H + t] = accl[n];
            d_gr[(long long)node * H + t] = accr[n];
        }
    }
}

// HW tanh (MUFU.TANH, 1 MUFU op) -> silu(x) = 0.5*x*(1 + tanh(x/2)).
// One MUFU per channel instead of two (EX2 + RCP for x/(1+exp(-x))).
__device__ __forceinline__ float fast_tanh(float x) {
    float r;
    asm("tanh.approx.f32 %0, %1;" : "=f"(r) : "f"(x));
    return r;
}
__device__ __forceinline__ float silu(float x) {
    return 0.5f * x * (1.0f + fast_tanh(0.5f * x));
}

// silu-dot helper: per-lane partial of aw . silu(a + b) over 4 channels.
__device__ __forceinline__ float silu_dot4(float4 a, float4 b, float4 aw4) {
    float x0 = a.x + b.x, x1 = a.y + b.y, x2 = a.z + b.z, x3 = a.w + b.w;
    return aw4.x * silu(x0) + aw4.y * silu(x1)
         + aw4.z * silu(x2) + aw4.w * silu(x3);
}

// CSR edge pass: one warp per dst node. gr[dst] loaded once; per edge we
// gather gl[src], compute v = (env+1e-7)*exp(p) (deferred-normalization
// softmax weight), accumulate numerator + denominator in registers, and
// write out[d] = acc / vsum once. No atomics, no out init, no norm pass.
// 2-way edge unroll overlaps the shuffle-reduce chains for ILP.
__global__ void k_edge_csr(const float* __restrict__ aw,
                           float* __restrict__ out, int N) {
    int lane = threadIdx.x & 31;
    long long warpId = ((long long)blockIdx.x * blockDim.x + threadIdx.x) >> 5;
    long long nWarps = ((long long)gridDim.x * blockDim.x) >> 5;
    float4 aw4 = ((const float4*)aw)[lane];

    for (long long d = warpId; d < N; d += nWarps) {
        int start = d_rowptr[d];
        int end   = d_rowptr[d + 1];
        float4 b = ((const float4*)d_gr)[d * 32 + lane];

        float4 acc = make_float4(0.f, 0.f, 0.f, 0.f);
        float vsum = 0.0f;

        int i = start;
        for (; i + 1 < end; i += 2) {
            int s0 = d_esrc[i], s1 = d_esrc[i + 1];
            float4 a0 = ((const float4*)d_gl)[(long long)s0 * 32 + lane];
            float4 a1 = ((const float4*)d_gl)[(long long)s1 * 32 + lane];
            float p0 = silu_dot4(a0, b, aw4);
            float p1 = silu_dot4(a1, b, aw4);
            #pragma unroll
            for (int off = 16; off; off >>= 1) {
                p0 += __shfl_xor_sync(0xFFFFFFFFu, p0, off);
                p1 += __shfl_xor_sync(0xFFFFFFFFu, p1, off);
            }
            float v0 = (d_eenv[i]     + 1e-7f) * __expf(p0);
            float v1 = (d_eenv[i + 1] + 1e-7f) * __expf(p1);
            acc.x = fmaf(v0, a0.x, fmaf(v1, a1.x, acc.x));
            acc.y = fmaf(v0, a0.y, fmaf(v1, a1.y, acc.y));
            acc.z = fmaf(v0, a0.z, fmaf(v1, a1.z, acc.z));
            acc.w = fmaf(v0, a0.w, fmaf(v1, a1.w, acc.w));
            vsum += v0 + v1;
        }
        if (i < end) {
            int s0 = d_esrc[i];
            float4 a0 = ((const float4*)d_gl)[(long long)s0 * 32 + lane];
            float p0 = silu_dot4(a0, b, aw4);
            #pragma unroll
            for (int off = 16; off; off >>= 1)
                p0 += __shfl_xor_sync(0xFFFFFFFFu, p0, off);
            float v0 = (d_eenv[i] + 1e-7f) * __expf(p0);
            acc.x = fmaf(v0, a0.x, acc.x);
            acc.y = fmaf(v0, a0.y, acc.y);
            acc.z = fmaf(v0, a0.z, acc.z);
            acc.w = fmaf(v0, a0.w, acc.w);
            vsum += v0;
        }

        float inv = (end > start) ? 1.0f / vsum : 0.0f;
        float4 o;
        o.x = acc.x * inv; o.y = acc.y * inv;
        o.z = acc.z * inv; o.w = acc.w * inv;
        ((float4*)out)[d * 32 + lane] = o;
    }
}

extern "C" void kernel_launch(void* const* d_in, const int* in_sizes, int n_in,
                              void* d_out, int out_size) {
    const float* q   = (const float*)d_in[0];
    // d_in[1]=k, d_in[2]=v : unused by the reference module
    const float* env = (const float*)d_in[3];
    const float* Wl  = (const float*)d_in[4];
    const float* Wr  = (const float*)d_in[5];
    const float* aw  = (const float*)d_in[6];
    const void*  ei  = d_in[7];

    int N = in_sizes[0] / H;
    long long E = in_sizes[3];
    float* out = (float*)d_out;

    long long n64 = (long long)in_sizes[7] / 2;
    int nb = (N + SCAN_T - 1) / SCAN_T;

    k_init_detect<<<(N + 255) / 256, 256>>>(ei, n64, N);
    k_hist<<<1024, 256>>>(ei, E);
    k_scan_local<<<nb, SCAN_T>>>(N);
    k_scan_bsum<<<1, SCAN_T>>>(nb);
    k_scan_add<<<nb, SCAN_T>>>(N, (int)E);
    k_scatter<<<1024, 256>>>(ei, env, E);

    k_gemm<<<(N + NPB - 1) / NPB, 128>>>(q, Wl, Wr, N);

    k_edge_csr<<<(N * 32 + 255) / 256, 256>>>(aw, out, N);
}